// round 14
// baseline (speedup 1.0000x reference)
#include <cuda_runtime.h>
#include <math.h>
#include <stdint.h>

// ----------------------------------------------------------------------------
// LiteTracker correlation-pyramid hot path.
//   corr (tf32 mma phase-4, per level): bilinear patch gather + 49x49x128
//        per-point GEMM -> g_x[l] [4096 x 2432] (2401 real cols + zeroed pad)
//   GEMM1 (tf32 mma): [16384 x 2432pad] @ w1[2401 x 384] + b1, exact GELU
//   GEMM2 (tf32 mma): [16384 x 384] @ w2[384 x 256] + b2 -> out[n,lvl*256+j]
// Inputs resolved BY ELEMENT COUNT (ordering-agnostic).
// ----------------------------------------------------------------------------

#define NPTS   4096
#define CCH    128
#define GSZ    7
#define GG     49
#define XDIM   2401
#define XPAD   2432      // 76 * 32
#define HID1   384
#define HID2   256
#define NLEV   4

__device__ float g_x[(size_t)NLEV * NPTS * XPAD];   // ~159 MB
__device__ float g_h[(size_t)NLEV * NPTS * HID1];   // ~25 MB

// ------------------------------ mma helpers ---------------------------------
__device__ __forceinline__ float f2tf32(float f) {
  unsigned r;
  asm("cvt.rna.tf32.f32 %0, %1;" : "=r"(r) : "f"(f));
  return __uint_as_float(r);
}

__device__ __forceinline__ void mma_tf32(
    float& c0, float& c1, float& c2, float& c3,
    unsigned a0, unsigned a1, unsigned a2, unsigned a3,
    unsigned b0, unsigned b1)
{
  asm volatile(
      "mma.sync.aligned.m16n8k8.row.col.f32.tf32.tf32.f32 "
      "{%0,%1,%2,%3}, {%4,%5,%6,%7}, {%8,%9}, {%10,%11,%12,%13};"
      : "=f"(c0), "=f"(c1), "=f"(c2), "=f"(c3)
      : "r"(a0), "r"(a1), "r"(a2), "r"(a3), "r"(b0), "r"(b1),
        "f"(c0), "f"(c1), "f"(c2), "f"(c3));
}

// ---------------------------- corr kernel -----------------------------------
// Smem layout:
//   St : [128][72]  sampled feats, k-major A-operand (hw padded 49->64, zeroed)
//        stride 72 (== 8 mod 32): A-fragment reads conflict-free.
//   PT : phase 1-2 patch [128][65]; phase 3-4 Tt [128][73] (odd stride:
//        conflict-free c-consecutive writes; frag reads ~conflict-free).
#define ST_STR 72
#define P_STR  65
#define T_STR  73
#define SMEM_ST_FLOATS (CCH * ST_STR)                 // 9216
#define SMEM_PT_FLOATS (CCH * T_STR)                  // 9344 (covers 65 too)
#define CORR_SMEM_BYTES ((SMEM_ST_FLOATS + SMEM_PT_FLOATS) * 4)  // 74240

struct CorrParams {
  const float* fm[4];
  const float* tf[4];
  const float* coords;
};

__global__ __launch_bounds__(256) void corr_kernel(CorrParams prm)
{
  extern __shared__ float sm[];
  float* St = sm;
  float* PT = sm + SMEM_ST_FLOATS;

  const int n     = blockIdx.x;
  const int level = blockIdx.y;
  const int tid   = threadIdx.x;

  const float* __restrict__ fmap  = prm.fm[level];
  const float* __restrict__ tfeat = prm.tf[level];
  const int H = 96 >> level;
  const int W = 128 >> level;
  const float scale = 1.f / (float)(1 << level);

  const float x  = prm.coords[2 * n + 0] * scale;
  const float y  = prm.coords[2 * n + 1] * scale;
  const float fx = floorf(x), fy = floorf(y);
  const float wx = x - fx,    wy = y - fy;
  const int ix0 = (int)fx - 3;
  const int iy0 = (int)fy - 3;
  const int HW  = H * W;

  // phase 1: 8x8 pixel patch for all 128 channels (zero outside image).
  for (int idx = tid; idx < CCH * 64; idx += 256) {
    const int c = idx >> 6, p = idx & 63;
    const int yy = p >> 3, xx = p & 7;
    const int gy = iy0 + yy, gx2 = ix0 + xx;
    float v = 0.f;
    if (gy >= 0 && gy < H && gx2 >= 0 && gx2 < W)
      v = fmap[c * HW + gy * W + gx2];
    PT[c * P_STR + p] = v;
  }
  __syncthreads();

  // phase 2: bilinear combine -> St[c][hw] (tf32-rounded), hw padded to 64.
  const float omx = 1.f - wx, omy = 1.f - wy;
  for (int idx = tid; idx < CCH * 64; idx += 256) {
    const int c = idx >> 6, hw = idx & 63;
    float r = 0.f;
    if (hw < GG) {
      const int h = hw / GSZ, w = hw - h * GSZ;
      const float* Pr = &PT[c * P_STR];
      const float v00 = Pr[w * 8 + h];
      const float v01 = Pr[w * 8 + h + 1];         // x+1
      const float v10 = Pr[(w + 1) * 8 + h];       // y+1
      const float v11 = Pr[(w + 1) * 8 + h + 1];
      r = f2tf32(omy * (omx * v00 + wx * v01) + wy * (omx * v10 + wx * v11));
    }
    St[c * ST_STR + hw] = r;
  }
  __syncthreads();

  // phase 3: template feats -> Tt[c][ij] (tf32-rounded), stride 73.
  const float* tf = tfeat + (size_t)n * CCH;
  for (int idx = tid; idx < GG * CCH; idx += 256) {
    const int ij = idx >> 7, c = idx & 127;
    PT[c * T_STR + ij] = f2tf32(tf[(size_t)ij * ((size_t)NPTS * CCH) + c]);
  }
  // zero pad cols ij 49..55 (N padded to 56)
  for (int idx = tid; idx < CCH * 8; idx += 256) {
    const int c = idx >> 3, j = idx & 7;
    if (j < 7) PT[c * T_STR + GG + j] = 0.f;
  }
  __syncthreads();

  // phase 4: C[49x49] = S[64x128] . T^T[128x56] via tf32 mma.
  const int warp = tid >> 5, lane = tid & 31;
  const int g  = lane >> 2, tg = lane & 3;
  const int wm = warp >> 1;
  const int half = warp & 1;
  const int m0 = wm * 16;
  const int nt0 = half * 4;
  const int ntn = half ? 3 : 4;

  float acc[4][4] = {};
  const unsigned* Su = (const unsigned*)St;
  const unsigned* Tu = (const unsigned*)PT;

  #pragma unroll
  for (int ks = 0; ks < 16; ++ks) {
    const int kb = ks * 8;
    const int abase = (kb + tg) * ST_STR + m0 + g;
    const unsigned a0 = Su[abase];
    const unsigned a1 = Su[abase + 8];
    const unsigned a2 = Su[abase + 4 * ST_STR];
    const unsigned a3 = Su[abase + 4 * ST_STR + 8];
    #pragma unroll
    for (int j = 0; j < 4; ++j) {
      if (j < ntn) {
        const int bbase = (kb + tg) * T_STR + (nt0 + j) * 8 + g;
        mma_tf32(acc[j][0], acc[j][1], acc[j][2], acc[j][3],
                 a0, a1, a2, a3, Tu[bbase], Tu[bbase + 4 * T_STR]);
      }
    }
  }

  float* xrow = &g_x[((size_t)level * NPTS + n) * XPAD];
  #pragma unroll
  for (int j = 0; j < 4; ++j) {
    if (j < ntn) {
      const int col = (nt0 + j) * 8 + 2 * tg;
      const int r0 = m0 + g, r1 = m0 + g + 8;
      if (r0 < GG) {
        if (col < GG)     xrow[r0 * GG + col]     = acc[j][0];
        if (col + 1 < GG) xrow[r0 * GG + col + 1] = acc[j][1];
      }
      if (r1 < GG) {
        if (col < GG)     xrow[r1 * GG + col]     = acc[j][2];
        if (col + 1 < GG) xrow[r1 * GG + col + 1] = acc[j][3];
      }
    }
  }
  // zero pad cols 2401..2431 of g_x row
  if (tid < XPAD - XDIM) xrow[XDIM + tid] = 0.f;
}

// ---------------------- GEMM1 (tf32 mma) + GELU -----------------------------
#define G1_ASTR 36
#define G1_BSTR 136
#define G1_ASF  (128 * G1_ASTR)
#define G1_BSF  (32 * G1_BSTR)
#define G1_SMEM_BYTES ((2 * (G1_ASF + G1_BSF)) * 4)   // 71680 B
#define G1_KT  (XPAD / 32)               // 76 exact k-tiles

__global__ __launch_bounds__(256) void gemm1_tc_kernel(
    const float* __restrict__ w1, const float* __restrict__ b1)
{
  extern __shared__ float sm1[];
  float* Asm[2] = { sm1, sm1 + G1_ASF };
  float* Bsm[2] = { sm1 + 2 * G1_ASF, sm1 + 2 * G1_ASF + G1_BSF };

  const int tid  = threadIdx.x;
  const int bm   = blockIdx.x * 128;
  const int bn   = blockIdx.y * 128;
  const int lane = tid & 31;
  const int warp = tid >> 5;
  const int wm   = warp >> 1;
  const int wn   = warp & 1;
  const int g    = lane >> 2;
  const int tg   = lane & 3;

  float acc[2][8][4] = {};
  float4 pa[4], pb[4];

  auto fetch = [&](int t) {
    const int k0 = t * 32;
    #pragma unroll
    for (int i = 0; i < 4; ++i) {
      const int idx = tid + i * 256;
      const int row = idx >> 3, f4 = (idx & 7) * 4;
      pa[i] = *(const float4*)&g_x[(size_t)(bm + row) * XPAD + k0 + f4];
      const int kr = idx >> 5, c4 = (idx & 31) * 4;
      const int kk = k0 + kr;
      pb[i] = (kk < XDIM)
          ? *(const float4*)&w1[(size_t)kk * HID1 + bn + c4]
          : make_float4(0.f, 0.f, 0.f, 0.f);
    }
  };
  auto stage = [&](int s) {
    float* Ad = Asm[s];
    float* Bd = Bsm[s];
    #pragma unroll
    for (int i = 0; i < 4; ++i) {
      const int idx = tid + i * 256;
      const int row = idx >> 3, f4 = (idx & 7) * 4;
      float* d = Ad + row * G1_ASTR + f4;
      d[0] = f2tf32(pa[i].x); d[1] = f2tf32(pa[i].y);
      d[2] = f2tf32(pa[i].z); d[3] = f2tf32(pa[i].w);
      const int kr = idx >> 5, c4 = (idx & 31) * 4;
      float* e = Bd + kr * G1_BSTR + c4;
      e[0] = f2tf32(pb[i].x); e[1] = f2tf32(pb[i].y);
      e[2] = f2tf32(pb[i].z); e[3] = f2tf32(pb[i].w);
    }
  };

  fetch(0);
  stage(0);
  __syncthreads();

  const int aoff = (wm * 32 + g) * G1_ASTR + tg;
  const int boff = tg * G1_BSTR + wn * 64 + g;

  for (int t = 0; t < G1_KT; ++t) {
    const int cur = t & 1;
    const bool hn = (t + 1 < G1_KT);
    if (hn) fetch(t + 1);

    const unsigned* Au = (const unsigned*)Asm[cur];
    const unsigned* Bu = (const unsigned*)Bsm[cur];
    #pragma unroll
    for (int ks = 0; ks < 4; ++ks) {
      const int kb = ks * 8;
      unsigned a[2][4], b[8][2];
      #pragma unroll
      for (int f = 0; f < 2; ++f) {
        const int base = aoff + f * 16 * G1_ASTR + kb;
        a[f][0] = Au[base];
        a[f][1] = Au[base + 8 * G1_ASTR];
        a[f][2] = Au[base + 4];
        a[f][3] = Au[base + 8 * G1_ASTR + 4];
      }
      const int bbase = boff + kb * G1_BSTR;
      #pragma unroll
      for (int j = 0; j < 8; ++j) {
        b[j][0] = Bu[bbase + j * 8];
        b[j][1] = Bu[bbase + j * 8 + 4 * G1_BSTR];
      }
      #pragma unroll
      for (int f = 0; f < 2; ++f)
        #pragma unroll
        for (int j = 0; j < 8; ++j)
          mma_tf32(acc[f][j][0], acc[f][j][1], acc[f][j][2], acc[f][j][3],
                   a[f][0], a[f][1], a[f][2], a[f][3], b[j][0], b[j][1]);
    }

    if (hn) {
      __syncthreads();
      stage(cur ^ 1);
      __syncthreads();
    }
  }

  #pragma unroll
  for (int f = 0; f < 2; ++f) {
    const int m0 = bm + wm * 32 + f * 16 + g;
    #pragma unroll
    for (int j = 0; j < 8; ++j) {
      const int col = bn + wn * 64 + j * 8 + 2 * tg;
      const float bi0 = b1[col], bi1 = b1[col + 1];
      float v0 = acc[f][j][0] + bi0;
      float v1 = acc[f][j][1] + bi1;
      float v2 = acc[f][j][2] + bi0;
      float v3 = acc[f][j][3] + bi1;
      v0 = 0.5f * v0 * (1.f + erff(v0 * 0.70710678118654752f));
      v1 = 0.5f * v1 * (1.f + erff(v1 * 0.70710678118654752f));
      v2 = 0.5f * v2 * (1.f + erff(v2 * 0.70710678118654752f));
      v3 = 0.5f * v3 * (1.f + erff(v3 * 0.70710678118654752f));
      *(float2*)&g_h[(size_t)m0 * HID1 + col] = make_float2(v0, v1);
      *(float2*)&g_h[(size_t)(m0 + 8) * HID1 + col] = make_float2(v2, v3);
    }
  }
}

// ---------------------- GEMM2 (tf32 mma) ------------------------------------
// Clone of gemm1_tc: [16384 x 384] @ w2[384 x 256] + b2, K=384 = 12 exact
// tiles, B row stride 256, epilogue scatters out[n, lvl*256 + col].
#define G2_KT (HID1 / 32)                // 12

__global__ __launch_bounds__(256) void gemm2_tc_kernel(
    const float* __restrict__ w2, const float* __restrict__ b2,
    float* __restrict__ out)
{
  extern __shared__ float sm2[];
  float* Asm[2] = { sm2, sm2 + G1_ASF };
  float* Bsm[2] = { sm2 + 2 * G1_ASF, sm2 + 2 * G1_ASF + G1_BSF };

  const int tid  = threadIdx.x;
  const int bm   = blockIdx.x * 128;
  const int bn   = blockIdx.y * 128;
  const int lane = tid & 31;
  const int warp = tid >> 5;
  const int wm   = warp >> 1;
  const int wn   = warp & 1;
  const int g    = lane >> 2;
  const int tg   = lane & 3;

  float acc[2][8][4] = {};
  float4 pa[4], pb[4];

  auto fetch = [&](int t) {
    const int k0 = t * 32;
    #pragma unroll
    for (int i = 0; i < 4; ++i) {
      const int idx = tid + i * 256;
      const int row = idx >> 3, f4 = (idx & 7) * 4;
      pa[i] = *(const float4*)&g_h[(size_t)(bm + row) * HID1 + k0 + f4];
      const int kr = idx >> 5, c4 = (idx & 31) * 4;
      pb[i] = *(const float4*)&w2[(size_t)(k0 + kr) * HID2 + bn + c4];
    }
  };
  auto stage = [&](int s) {
    float* Ad = Asm[s];
    float* Bd = Bsm[s];
    #pragma unroll
    for (int i = 0; i < 4; ++i) {
      const int idx = tid + i * 256;
      const int row = idx >> 3, f4 = (idx & 7) * 4;
      float* d = Ad + row * G1_ASTR + f4;
      d[0] = f2tf32(pa[i].x); d[1] = f2tf32(pa[i].y);
      d[2] = f2tf32(pa[i].z); d[3] = f2tf32(pa[i].w);
      const int kr = idx >> 5, c4 = (idx & 31) * 4;
      float* e = Bd + kr * G1_BSTR + c4;
      e[0] = f2tf32(pb[i].x); e[1] = f2tf32(pb[i].y);
      e[2] = f2tf32(pb[i].z); e[3] = f2tf32(pb[i].w);
    }
  };

  fetch(0);
  stage(0);
  __syncthreads();

  const int aoff = (wm * 32 + g) * G1_ASTR + tg;
  const int boff = tg * G1_BSTR + wn * 64 + g;

  for (int t = 0; t < G2_KT; ++t) {
    const int cur = t & 1;
    const bool hn = (t + 1 < G2_KT);
    if (hn) fetch(t + 1);

    const unsigned* Au = (const unsigned*)Asm[cur];
    const unsigned* Bu = (const unsigned*)Bsm[cur];
    #pragma unroll
    for (int ks = 0; ks < 4; ++ks) {
      const int kb = ks * 8;
      unsigned a[2][4], b[8][2];
      #pragma unroll
      for (int f = 0; f < 2; ++f) {
        const int base = aoff + f * 16 * G1_ASTR + kb;
        a[f][0] = Au[base];
        a[f][1] = Au[base + 8 * G1_ASTR];
        a[f][2] = Au[base + 4];
        a[f][3] = Au[base + 8 * G1_ASTR + 4];
      }
      const int bbase = boff + kb * G1_BSTR;
      #pragma unroll
      for (int j = 0; j < 8; ++j) {
        b[j][0] = Bu[bbase + j * 8];
        b[j][1] = Bu[bbase + j * 8 + 4 * G1_BSTR];
      }
      #pragma unroll
      for (int f = 0; f < 2; ++f)
        #pragma unroll
        for (int j = 0; j < 8; ++j)
          mma_tf32(acc[f][j][0], acc[f][j][1], acc[f][j][2], acc[f][j][3],
                   a[f][0], a[f][1], a[f][2], a[f][3], b[j][0], b[j][1]);
    }

    if (hn) {
      __syncthreads();
      stage(cur ^ 1);
      __syncthreads();
    }
  }

  // epilogue: bias, scatter to out[n, lvl*256 + (bn + col)]
  #pragma unroll
  for (int f = 0; f < 2; ++f) {
    const int m0 = bm + wm * 32 + f * 16 + g;       // row in [0,16384)
    const int n0   = m0 & (NPTS - 1);
    const int lvl0 = m0 >> 12;
    const int m1 = m0 + 8;
    const int n1   = m1 & (NPTS - 1);
    const int lvl1 = m1 >> 12;
    #pragma unroll
    for (int j = 0; j < 8; ++j) {
      const int col = bn + wn * 64 + j * 8 + 2 * tg;
      const float bi0 = b2[col], bi1 = b2[col + 1];
      *(float2*)&out[(size_t)n0 * (NLEV * HID2) + lvl0 * HID2 + col] =
          make_float2(acc[f][j][0] + bi0, acc[f][j][1] + bi1);
      *(float2*)&out[(size_t)n1 * (NLEV * HID2) + lvl1 * HID2 + col] =
          make_float2(acc[f][j][2] + bi0, acc[f][j][3] + bi1);
    }
  }
}

// ------------------------------- launch -------------------------------------
// Resolve inputs purely by element count (ordering-agnostic):
//   tfeat*  : 25690112 (x4, order of appearance = level 0..3)
//   fmaps0  : 1572864, fmaps1: 393216, fmaps3: 24576  (unique)
//   98304   : first occurrence = fmaps2, second = w2
//   coords  : 8192, w1: 921984, b1: 384, b2: 256
extern "C" void kernel_launch(void* const* d_in, const int* in_sizes, int n_in,
                              void* d_out, int out_size)
{
  CorrParams prm;
  const float *w1 = 0, *b1 = 0, *w2 = 0, *b2 = 0;
  int ntf = 0, n98k = 0;

  for (int i = 0; i < n_in; ++i) {
    const float* p = (const float*)d_in[i];
    switch (in_sizes[i]) {
      case 25690112: if (ntf < 4) prm.tf[ntf++] = p; break;
      case 1572864:  prm.fm[0] = p; break;
      case 393216:   prm.fm[1] = p; break;
      case 98304:    if (n98k++ == 0) prm.fm[2] = p; else w2 = p; break;
      case 24576:    prm.fm[3] = p; break;
      case 8192:     prm.coords = p; break;
      case 921984:   w1 = p; break;
      case 384:      b1 = p; break;
      case 256:      b2 = p; break;
      default: break;
    }
  }

  cudaFuncSetAttribute(corr_kernel, cudaFuncAttributeMaxDynamicSharedMemorySize,
                       CORR_SMEM_BYTES);
  cudaFuncSetAttribute(gemm1_tc_kernel,
                       cudaFuncAttributeMaxDynamicSharedMemorySize,
                       G1_SMEM_BYTES);
  cudaFuncSetAttribute(gemm2_tc_kernel,
                       cudaFuncAttributeMaxDynamicSharedMemorySize,
                       G1_SMEM_BYTES);

  corr_kernel<<<dim3(NPTS, NLEV), 256, CORR_SMEM_BYTES>>>(prm);
  gemm1_tc_kernel<<<dim3(16384 / 128, HID1 / 128), 256, G1_SMEM_BYTES>>>(w1, b1);
  gemm2_tc_kernel<<<dim3(16384 / 128, HID2 / 128), 256, G1_SMEM_BYTES>>>(
      w2, b2, (float*)d_out);
}

// round 15
// speedup vs baseline: 1.3237x; 1.3237x over previous
#include <cuda_runtime.h>
#include <math.h>
#include <stdint.h>

// ----------------------------------------------------------------------------
// LiteTracker correlation-pyramid hot path.
//   corr (tf32 mma, 2-chunk channel pipeline): bilinear patch gather +
//        49x49x128 per-point GEMM -> g_x[l] [4096 x 2432]
//   GEMM1 (tf32 mma): [16384 x 2432pad] @ w1[2401 x 384] + b1, exact GELU
//   GEMM2 (tf32 mma): [16384 x 384] @ w2[384 x 256] + b2 -> out[n,lvl*256+j]
// Inputs resolved BY ELEMENT COUNT (ordering-agnostic).
// ----------------------------------------------------------------------------

#define NPTS   4096
#define CCH    128
#define CH     64        // channels per chunk (2 chunks)
#define GSZ    7
#define GG     49
#define XDIM   2401
#define XPAD   2432      // 76 * 32
#define HID1   384
#define HID2   256
#define NLEV   4

__device__ float g_x[(size_t)NLEV * NPTS * XPAD];   // ~159 MB
__device__ float g_h[(size_t)NLEV * NPTS * HID1];   // ~25 MB

// ------------------------------ mma helpers ---------------------------------
__device__ __forceinline__ float f2tf32(float f) {
  unsigned r;
  asm("cvt.rna.tf32.f32 %0, %1;" : "=r"(r) : "f"(f));
  return __uint_as_float(r);
}

__device__ __forceinline__ void mma_tf32(
    float& c0, float& c1, float& c2, float& c3,
    unsigned a0, unsigned a1, unsigned a2, unsigned a3,
    unsigned b0, unsigned b1)
{
  asm volatile(
      "mma.sync.aligned.m16n8k8.row.col.f32.tf32.tf32.f32 "
      "{%0,%1,%2,%3}, {%4,%5,%6,%7}, {%8,%9}, {%10,%11,%12,%13};"
      : "=f"(c0), "=f"(c1), "=f"(c2), "=f"(c3)
      : "r"(a0), "r"(a1), "r"(a2), "r"(a3), "r"(b0), "r"(b1),
        "f"(c0), "f"(c1), "f"(c2), "f"(c3));
}

// ---------------------------- corr kernel -----------------------------------
// Channel-chunked (2 x 64ch) to shrink smem 74KB -> 35KB => 6 blocks/SM.
//   St : [64][72]  sampled feats chunk, k-major A-operand (hw pad 49->64, 0)
//        stride 72 (== 8 mod 32): A-fragment reads conflict-free.
//   R2 : phase 1-2 patch [64][65]; phase 3-4 Tt [64][57] (odd stride).
#define ST_STR 72
#define P_STR  65
#define T_STR  57
#define SMEM_ST_FLOATS (CH * ST_STR)                  // 4608
#define SMEM_R2_FLOATS (CH * P_STR)                   // 4160 (covers Tt 3648)
#define CORR_SMEM_BYTES ((SMEM_ST_FLOATS + SMEM_R2_FLOATS) * 4)  // 35072

struct CorrParams {
  const float* fm[4];
  const float* tf[4];
  const float* coords;
};

__global__ __launch_bounds__(256, 6) void corr_kernel(CorrParams prm)
{
  extern __shared__ float sm[];
  float* St = sm;
  float* R2 = sm + SMEM_ST_FLOATS;

  const int n     = blockIdx.x;
  const int level = blockIdx.y;
  const int tid   = threadIdx.x;

  const float* __restrict__ fmap  = prm.fm[level];
  const float* __restrict__ tfeat = prm.tf[level];
  const int H = 96 >> level;
  const int W = 128 >> level;
  const float scale = 1.f / (float)(1 << level);

  const float x  = prm.coords[2 * n + 0] * scale;
  const float y  = prm.coords[2 * n + 1] * scale;
  const float fx = floorf(x), fy = floorf(y);
  const float wx = x - fx,    wy = y - fy;
  const int ix0 = (int)fx - 3;
  const int iy0 = (int)fy - 3;
  const int HW  = H * W;
  const float omx = 1.f - wx, omy = 1.f - wy;

  const int warp = tid >> 5, lane = tid & 31;
  const int g  = lane >> 2, tg = lane & 3;
  const int wm = warp >> 1;
  const int half = warp & 1;
  const int m0 = wm * 16;
  const int nt0 = half * 4;
  const int ntn = half ? 3 : 4;

  const float* tf = tfeat + (size_t)n * CCH;
  float acc[4][4] = {};

  #pragma unroll
  for (int q = 0; q < 2; ++q) {
    const int cbase = q * CH;
    __syncthreads();   // prior chunk's phase-4 reads of St/R2 complete

    // phase 1: 8x8 pixel patch for 64 channels (zero outside image).
    for (int idx = tid; idx < CH * 64; idx += 256) {
      const int c = idx >> 6, p = idx & 63;
      const int yy = p >> 3, xx = p & 7;
      const int gy = iy0 + yy, gx2 = ix0 + xx;
      float v = 0.f;
      if (gy >= 0 && gy < H && gx2 >= 0 && gx2 < W)
        v = fmap[(cbase + c) * HW + gy * W + gx2];
      R2[c * P_STR + p] = v;
    }
    __syncthreads();

    // phase 2: bilinear combine -> St[c][hw] (tf32), hw padded to 64 (zeros).
    for (int idx = tid; idx < CH * 64; idx += 256) {
      const int c = idx >> 6, hw = idx & 63;
      float r = 0.f;
      if (hw < GG) {
        const int h = hw / GSZ, w = hw - h * GSZ;
        const float* Pr = &R2[c * P_STR];
        const float v00 = Pr[w * 8 + h];
        const float v01 = Pr[w * 8 + h + 1];         // x+1
        const float v10 = Pr[(w + 1) * 8 + h];       // y+1
        const float v11 = Pr[(w + 1) * 8 + h + 1];
        r = f2tf32(omy * (omx * v00 + wx * v01) + wy * (omx * v10 + wx * v11));
      }
      St[c * ST_STR + hw] = r;
    }
    __syncthreads();   // phase-2 reads of patch done before Tt overwrites R2

    // phase 3: template feats -> Tt[c][ij] (tf32), stride 57 (odd).
    for (int idx = tid; idx < GG * CH; idx += 256) {
      const int ij = idx >> 6, c = idx & 63;
      R2[c * T_STR + ij] =
          f2tf32(tf[(size_t)ij * ((size_t)NPTS * CCH) + cbase + c]);
    }
    // zero pad cols ij 49..55 (N padded to 56)
    for (int idx = tid; idx < CH * 8; idx += 256) {
      const int c = idx >> 3, j = idx & 7;
      if (j < 7) R2[c * T_STR + GG + j] = 0.f;
    }
    __syncthreads();

    // phase 4: accumulate C += S_chunk[64x64k] . T_chunk^T[64k x 56]
    const unsigned* Su = (const unsigned*)St;
    const unsigned* Tu = (const unsigned*)R2;
    #pragma unroll
    for (int ks = 0; ks < 8; ++ks) {
      const int kb = ks * 8;
      const int abase = (kb + tg) * ST_STR + m0 + g;
      const unsigned a0 = Su[abase];
      const unsigned a1 = Su[abase + 8];
      const unsigned a2 = Su[abase + 4 * ST_STR];
      const unsigned a3 = Su[abase + 4 * ST_STR + 8];
      #pragma unroll
      for (int j = 0; j < 4; ++j) {
        if (j < ntn) {
          const int bbase = (kb + tg) * T_STR + (nt0 + j) * 8 + g;
          mma_tf32(acc[j][0], acc[j][1], acc[j][2], acc[j][3],
                   a0, a1, a2, a3, Tu[bbase], Tu[bbase + 4 * T_STR]);
        }
      }
    }
  }

  float* xrow = &g_x[((size_t)level * NPTS + n) * XPAD];
  #pragma unroll
  for (int j = 0; j < 4; ++j) {
    if (j < ntn) {
      const int col = (nt0 + j) * 8 + 2 * tg;
      const int r0 = m0 + g, r1 = m0 + g + 8;
      if (r0 < GG) {
        if (col < GG)     xrow[r0 * GG + col]     = acc[j][0];
        if (col + 1 < GG) xrow[r0 * GG + col + 1] = acc[j][1];
      }
      if (r1 < GG) {
        if (col < GG)     xrow[r1 * GG + col]     = acc[j][2];
        if (col + 1 < GG) xrow[r1 * GG + col + 1] = acc[j][3];
      }
    }
  }
  // zero pad cols 2401..2431 of g_x row
  if (tid < XPAD - XDIM) xrow[XDIM + tid] = 0.f;
}

// ---------------------- GEMM1 (tf32 mma) + GELU -----------------------------
// Grid (N-tiles, M-tiles): bn siblings schedule-adjacent -> A tiles shared
// via L2 (cuts g_x DRAM re-reads 3x -> ~1x).
#define G1_ASTR 36
#define G1_BSTR 136
#define G1_ASF  (128 * G1_ASTR)
#define G1_BSF  (32 * G1_BSTR)
#define G1_SMEM_BYTES ((2 * (G1_ASF + G1_BSF)) * 4)   // 71680 B
#define G1_KT  (XPAD / 32)               // 76 exact k-tiles

__global__ __launch_bounds__(256) void gemm1_tc_kernel(
    const float* __restrict__ w1, const float* __restrict__ b1)
{
  extern __shared__ float sm1[];
  float* Asm[2] = { sm1, sm1 + G1_ASF };
  float* Bsm[2] = { sm1 + 2 * G1_ASF, sm1 + 2 * G1_ASF + G1_BSF };

  const int tid  = threadIdx.x;
  const int bm   = blockIdx.y * 128;   // swapped: y = M-tile
  const int bn   = blockIdx.x * 128;   // swapped: x = N-tile (adjacent)
  const int lane = tid & 31;
  const int warp = tid >> 5;
  const int wm   = warp >> 1;
  const int wn   = warp & 1;
  const int g    = lane >> 2;
  const int tg   = lane & 3;

  float acc[2][8][4] = {};
  float4 pa[4], pb[4];

  auto fetch = [&](int t) {
    const int k0 = t * 32;
    #pragma unroll
    for (int i = 0; i < 4; ++i) {
      const int idx = tid + i * 256;
      const int row = idx >> 3, f4 = (idx & 7) * 4;
      pa[i] = *(const float4*)&g_x[(size_t)(bm + row) * XPAD + k0 + f4];
      const int kr = idx >> 5, c4 = (idx & 31) * 4;
      const int kk = k0 + kr;
      pb[i] = (kk < XDIM)
          ? *(const float4*)&w1[(size_t)kk * HID1 + bn + c4]
          : make_float4(0.f, 0.f, 0.f, 0.f);
    }
  };
  auto stage = [&](int s) {
    float* Ad = Asm[s];
    float* Bd = Bsm[s];
    #pragma unroll
    for (int i = 0; i < 4; ++i) {
      const int idx = tid + i * 256;
      const int row = idx >> 3, f4 = (idx & 7) * 4;
      float* d = Ad + row * G1_ASTR + f4;
      d[0] = f2tf32(pa[i].x); d[1] = f2tf32(pa[i].y);
      d[2] = f2tf32(pa[i].z); d[3] = f2tf32(pa[i].w);
      const int kr = idx >> 5, c4 = (idx & 31) * 4;
      float* e = Bd + kr * G1_BSTR + c4;
      e[0] = f2tf32(pb[i].x); e[1] = f2tf32(pb[i].y);
      e[2] = f2tf32(pb[i].z); e[3] = f2tf32(pb[i].w);
    }
  };

  fetch(0);
  stage(0);
  __syncthreads();

  const int aoff = (wm * 32 + g) * G1_ASTR + tg;
  const int boff = tg * G1_BSTR + wn * 64 + g;

  for (int t = 0; t < G1_KT; ++t) {
    const int cur = t & 1;
    const bool hn = (t + 1 < G1_KT);
    if (hn) fetch(t + 1);

    const unsigned* Au = (const unsigned*)Asm[cur];
    const unsigned* Bu = (const unsigned*)Bsm[cur];
    #pragma unroll
    for (int ks = 0; ks < 4; ++ks) {
      const int kb = ks * 8;
      unsigned a[2][4], b[8][2];
      #pragma unroll
      for (int f = 0; f < 2; ++f) {
        const int base = aoff + f * 16 * G1_ASTR + kb;
        a[f][0] = Au[base];
        a[f][1] = Au[base + 8 * G1_ASTR];
        a[f][2] = Au[base + 4];
        a[f][3] = Au[base + 8 * G1_ASTR + 4];
      }
      const int bbase = boff + kb * G1_BSTR;
      #pragma unroll
      for (int j = 0; j < 8; ++j) {
        b[j][0] = Bu[bbase + j * 8];
        b[j][1] = Bu[bbase + j * 8 + 4 * G1_BSTR];
      }
      #pragma unroll
      for (int f = 0; f < 2; ++f)
        #pragma unroll
        for (int j = 0; j < 8; ++j)
          mma_tf32(acc[f][j][0], acc[f][j][1], acc[f][j][2], acc[f][j][3],
                   a[f][0], a[f][1], a[f][2], a[f][3], b[j][0], b[j][1]);
    }

    if (hn) {
      __syncthreads();
      stage(cur ^ 1);
      __syncthreads();
    }
  }

  #pragma unroll
  for (int f = 0; f < 2; ++f) {
    const int m0 = bm + wm * 32 + f * 16 + g;
    #pragma unroll
    for (int j = 0; j < 8; ++j) {
      const int col = bn + wn * 64 + j * 8 + 2 * tg;
      const float bi0 = b1[col], bi1 = b1[col + 1];
      float v0 = acc[f][j][0] + bi0;
      float v1 = acc[f][j][1] + bi1;
      float v2 = acc[f][j][2] + bi0;
      float v3 = acc[f][j][3] + bi1;
      v0 = 0.5f * v0 * (1.f + erff(v0 * 0.70710678118654752f));
      v1 = 0.5f * v1 * (1.f + erff(v1 * 0.70710678118654752f));
      v2 = 0.5f * v2 * (1.f + erff(v2 * 0.70710678118654752f));
      v3 = 0.5f * v3 * (1.f + erff(v3 * 0.70710678118654752f));
      *(float2*)&g_h[(size_t)m0 * HID1 + col] = make_float2(v0, v1);
      *(float2*)&g_h[(size_t)(m0 + 8) * HID1 + col] = make_float2(v2, v3);
    }
  }
}

// ---------------------- GEMM2 (tf32 mma) ------------------------------------
#define G2_KT (HID1 / 32)                // 12

__global__ __launch_bounds__(256) void gemm2_tc_kernel(
    const float* __restrict__ w2, const float* __restrict__ b2,
    float* __restrict__ out)
{
  extern __shared__ float sm2[];
  float* Asm[2] = { sm2, sm2 + G1_ASF };
  float* Bsm[2] = { sm2 + 2 * G1_ASF, sm2 + 2 * G1_ASF + G1_BSF };

  const int tid  = threadIdx.x;
  const int bm   = blockIdx.y * 128;   // swapped
  const int bn   = blockIdx.x * 128;   // swapped
  const int lane = tid & 31;
  const int warp = tid >> 5;
  const int wm   = warp >> 1;
  const int wn   = warp & 1;
  const int g    = lane >> 2;
  const int tg   = lane & 3;

  float acc[2][8][4] = {};
  float4 pa[4], pb[4];

  auto fetch = [&](int t) {
    const int k0 = t * 32;
    #pragma unroll
    for (int i = 0; i < 4; ++i) {
      const int idx = tid + i * 256;
      const int row = idx >> 3, f4 = (idx & 7) * 4;
      pa[i] = *(const float4*)&g_h[(size_t)(bm + row) * HID1 + k0 + f4];
      const int kr = idx >> 5, c4 = (idx & 31) * 4;
      pb[i] = *(const float4*)&w2[(size_t)(k0 + kr) * HID2 + bn + c4];
    }
  };
  auto stage = [&](int s) {
    float* Ad = Asm[s];
    float* Bd = Bsm[s];
    #pragma unroll
    for (int i = 0; i < 4; ++i) {
      const int idx = tid + i * 256;
      const int row = idx >> 3, f4 = (idx & 7) * 4;
      float* d = Ad + row * G1_ASTR + f4;
      d[0] = f2tf32(pa[i].x); d[1] = f2tf32(pa[i].y);
      d[2] = f2tf32(pa[i].z); d[3] = f2tf32(pa[i].w);
      const int kr = idx >> 5, c4 = (idx & 31) * 4;
      float* e = Bd + kr * G1_BSTR + c4;
      e[0] = f2tf32(pb[i].x); e[1] = f2tf32(pb[i].y);
      e[2] = f2tf32(pb[i].z); e[3] = f2tf32(pb[i].w);
    }
  };

  fetch(0);
  stage(0);
  __syncthreads();

  const int aoff = (wm * 32 + g) * G1_ASTR + tg;
  const int boff = tg * G1_BSTR + wn * 64 + g;

  for (int t = 0; t < G2_KT; ++t) {
    const int cur = t & 1;
    const bool hn = (t + 1 < G2_KT);
    if (hn) fetch(t + 1);

    const unsigned* Au = (const unsigned*)Asm[cur];
    const unsigned* Bu = (const unsigned*)Bsm[cur];
    #pragma unroll
    for (int ks = 0; ks < 4; ++ks) {
      const int kb = ks * 8;
      unsigned a[2][4], b[8][2];
      #pragma unroll
      for (int f = 0; f < 2; ++f) {
        const int base = aoff + f * 16 * G1_ASTR + kb;
        a[f][0] = Au[base];
        a[f][1] = Au[base + 8 * G1_ASTR];
        a[f][2] = Au[base + 4];
        a[f][3] = Au[base + 8 * G1_ASTR + 4];
      }
      const int bbase = boff + kb * G1_BSTR;
      #pragma unroll
      for (int j = 0; j < 8; ++j) {
        b[j][0] = Bu[bbase + j * 8];
        b[j][1] = Bu[bbase + j * 8 + 4 * G1_BSTR];
      }
      #pragma unroll
      for (int f = 0; f < 2; ++f)
        #pragma unroll
        for (int j = 0; j < 8; ++j)
          mma_tf32(acc[f][j][0], acc[f][j][1], acc[f][j][2], acc[f][j][3],
                   a[f][0], a[f][1], a[f][2], a[f][3], b[j][0], b[j][1]);
    }

    if (hn) {
      __syncthreads();
      stage(cur ^ 1);
      __syncthreads();
    }
  }

  // epilogue: bias, scatter to out[n, lvl*256 + (bn + col)]
  #pragma unroll
  for (int f = 0; f < 2; ++f) {
    const int m0 = bm + wm * 32 + f * 16 + g;       // row in [0,16384)
    const int n0   = m0 & (NPTS - 1);
    const int lvl0 = m0 >> 12;
    const int m1 = m0 + 8;
    const int n1   = m1 & (NPTS - 1);
    const int lvl1 = m1 >> 12;
    #pragma unroll
    for (int j = 0; j < 8; ++j) {
      const int col = bn + wn * 64 + j * 8 + 2 * tg;
      const float bi0 = b2[col], bi1 = b2[col + 1];
      *(float2*)&out[(size_t)n0 * (NLEV * HID2) + lvl0 * HID2 + col] =
          make_float2(acc[f][j][0] + bi0, acc[f][j][1] + bi1);
      *(float2*)&out[(size_t)n1 * (NLEV * HID2) + lvl1 * HID2 + col] =
          make_float2(acc[f][j][2] + bi0, acc[f][j][3] + bi1);
    }
  }
}

// ------------------------------- launch -------------------------------------
// Resolve inputs purely by element count (ordering-agnostic):
//   tfeat*  : 25690112 (x4, order of appearance = level 0..3)
//   fmaps0  : 1572864, fmaps1: 393216, fmaps3: 24576  (unique)
//   98304   : first occurrence = fmaps2, second = w2
//   coords  : 8192, w1: 921984, b1: 384, b2: 256
extern "C" void kernel_launch(void* const* d_in, const int* in_sizes, int n_in,
                              void* d_out, int out_size)
{
  CorrParams prm;
  const float *w1 = 0, *b1 = 0, *w2 = 0, *b2 = 0;
  int ntf = 0, n98k = 0;

  for (int i = 0; i < n_in; ++i) {
    const float* p = (const float*)d_in[i];
    switch (in_sizes[i]) {
      case 25690112: if (ntf < 4) prm.tf[ntf++] = p; break;
      case 1572864:  prm.fm[0] = p; break;
      case 393216:   prm.fm[1] = p; break;
      case 98304:    if (n98k++ == 0) prm.fm[2] = p; else w2 = p; break;
      case 24576:    prm.fm[3] = p; break;
      case 8192:     prm.coords = p; break;
      case 921984:   w1 = p; break;
      case 384:      b1 = p; break;
      case 256:      b2 = p; break;
      default: break;
    }
  }

  cudaFuncSetAttribute(corr_kernel, cudaFuncAttributeMaxDynamicSharedMemorySize,
                       CORR_SMEM_BYTES);
  cudaFuncSetAttribute(gemm1_tc_kernel,
                       cudaFuncAttributeMaxDynamicSharedMemorySize,
                       G1_SMEM_BYTES);
  cudaFuncSetAttribute(gemm2_tc_kernel,
                       cudaFuncAttributeMaxDynamicSharedMemorySize,
                       G1_SMEM_BYTES);

  corr_kernel<<<dim3(NPTS, NLEV), 256, CORR_SMEM_BYTES>>>(prm);
  gemm1_tc_kernel<<<dim3(HID1 / 128, 16384 / 128), 256, G1_SMEM_BYTES>>>(w1, b1);
  gemm2_tc_kernel<<<dim3(HID2 / 128, 16384 / 128), 256, G1_SMEM_BYTES>>>(
      w2, b2, (float*)d_out);
}